// round 3
// baseline (speedup 1.0000x reference)
#include <cuda_runtime.h>
#include <cuda_bf16.h>

#define B_      8
#define NVAL    1024
#define MVAL    1024
#define CIN     8
#define CREP    9
#define COUT    16

#define MBLK    64                 // m-values per block (2 per thread-lane)
#define NSPLIT  16                 // n-chunks per block (warp = chunk)
#define NTHREADS (32 * NSPLIT)     // 512
#define NCHUNK  (NVAL / NSPLIT)    // 64

typedef unsigned long long u64;

__device__ __forceinline__ u64 pack2(float lo, float hi) {
    u64 r; asm("mov.b64 %0, {%1, %2};" : "=l"(r) : "f"(lo), "f"(hi)); return r;
}
__device__ __forceinline__ void unpack2(u64 v, float& lo, float& hi) {
    asm("mov.b64 {%0, %1}, %2;" : "=f"(lo), "=f"(hi) : "l"(v));
}
__device__ __forceinline__ u64 add2(u64 a, u64 b) {
    u64 r; asm("add.rn.f32x2 %0, %1, %2;" : "=l"(r) : "l"(a), "l"(b)); return r;
}
__device__ __forceinline__ u64 mul2(u64 a, u64 b) {
    u64 r; asm("mul.rn.f32x2 %0, %1, %2;" : "=l"(r) : "l"(a), "l"(b)); return r;
}
__device__ __forceinline__ u64 fma2(u64 a, u64 b, u64 c) {
    u64 r; asm("fma.rn.f32x2 %0, %1, %2, %3;" : "=l"(r) : "l"(a), "l"(b), "l"(c)); return r;
}
__device__ __forceinline__ float ex2(float x) {   // MUFU.EX2
    float r; asm("ex2.approx.f32 %0, %1;" : "=f"(r) : "f"(x)); return r;
}

// One shared pool, two phases:
//  phase 1 (main loop): [0,1024) = sf*x, [1024,2048) = -sf*x, [2048,10240) = y
//  phase 2 (reduction): [0, 9216) = partials [NSPLIT][MBLK][CREP]
__global__ __launch_bounds__(NTHREADS)
void convcnp_kernel(const float* __restrict__ gx,
                    const float* __restrict__ gy,
                    const float* __restrict__ gt,
                    const float* __restrict__ gsigma,
                    const float* __restrict__ gW,
                    const float* __restrict__ gbias,
                    float* __restrict__ gout)
{
    __shared__ float smem[2 * NVAL + NVAL * CIN];   // 40KB
    float* s_x  = smem;
    float* s_xn = smem + NVAL;
    float* s_y  = smem + 2 * NVAL;

    const int b    = blockIdx.x / (MVAL / MBLK);
    const int mt   = blockIdx.x % (MVAL / MBLK);
    const int tid  = threadIdx.x;
    const int lane = tid & 31;
    const int ns   = tid >> 5;

    // Per-channel exponent coefficients: kk[c] = -0.5*log2e / scale_c^2
    float kk[CREP];
    bool same = true;
    #pragma unroll
    for (int c = 0; c < CREP; c++) {
        float s = __expf(gsigma[c]);
        kk[c] = -0.5f * 1.4426950408889634f / (s * s);
        if (c > 0 && kk[c] != kk[0]) same = false;
    }
    const float sf = same ? sqrtf(-kk[0]) : 1.0f;

    // Stage scaled x, negated scaled x, and y into shared
    for (int i = tid; i < NVAL; i += NTHREADS) {
        float v = gx[b * NVAL + i] * sf;
        s_x [i] =  v;
        s_xn[i] = -v;
    }
    {
        const float4* y4 = (const float4*)(gy + b * NVAL * CIN);
        float4* sy4 = (float4*)s_y;
        #pragma unroll
        for (int i = tid; i < NVAL * CIN / 4; i += NTHREADS)
            sy4[i] = y4[i];
    }
    const int   m0  = mt * MBLK + lane;        // this thread's two m-points
    const int   m1  = m0 + 32;
    const float tmA = gt[b * MVAL + m0] * sf;
    const float tmB = gt[b * MVAL + m1] * sf;
    __syncthreads();

    const int n0 = ns * NCHUNK;
    float sumA[CREP], sumB[CREP];

    if (same) {
        const u64 ttA  = pack2( tmA,  tmA), nttA = pack2(-tmA, -tmA);
        const u64 ttB  = pack2( tmB,  tmB), nttB = pack2(-tmB, -tmB);
        u64 dA = 0, A12 = 0, A34 = 0, A56 = 0, A78 = 0;
        u64 dB = 0, B12 = 0, B34 = 0, B56 = 0, B78 = 0;

        #pragma unroll 4
        for (int n = n0; n < n0 + NCHUNK; n += 2) {
            u64 x2  = *(const u64*)&s_x [n];
            u64 xn2 = *(const u64*)&s_xn[n];
            ulonglong2 yA = *(const ulonglong2*)&s_y[n * CIN];
            ulonglong2 yB = *(const ulonglong2*)&s_y[n * CIN + 4];
            ulonglong2 zA = *(const ulonglong2*)&s_y[(n + 1) * CIN];
            ulonglong2 zB = *(const ulonglong2*)&s_y[(n + 1) * CIN + 4];

            // m0 chain
            u64 dd = mul2(add2(x2, nttA), add2(xn2, ttA));   // -(x-t)^2, pre-scaled
            float d0, d1; unpack2(dd, d0, d1);
            float e0 = ex2(d0), e1 = ex2(d1);
            dA = add2(dA, pack2(e0, e1));
            u64 e00 = pack2(e0, e0), e11 = pack2(e1, e1);
            A12 = fma2(e00, yA.x, A12);  A34 = fma2(e00, yA.y, A34);
            A56 = fma2(e00, yB.x, A56);  A78 = fma2(e00, yB.y, A78);
            A12 = fma2(e11, zA.x, A12);  A34 = fma2(e11, zA.y, A34);
            A56 = fma2(e11, zB.x, A56);  A78 = fma2(e11, zB.y, A78);

            // m1 chain (independent)
            u64 gg = mul2(add2(x2, nttB), add2(xn2, ttB));
            float g0, g1; unpack2(gg, g0, g1);
            float f0 = ex2(g0), f1 = ex2(g1);
            dB = add2(dB, pack2(f0, f1));
            u64 f00 = pack2(f0, f0), f11 = pack2(f1, f1);
            B12 = fma2(f00, yA.x, B12);  B34 = fma2(f00, yA.y, B34);
            B56 = fma2(f00, yB.x, B56);  B78 = fma2(f00, yB.y, B78);
            B12 = fma2(f11, zA.x, B12);  B34 = fma2(f11, zA.y, B34);
            B56 = fma2(f11, zB.x, B56);  B78 = fma2(f11, zB.y, B78);
        }
        float lo, hi;
        unpack2(dA, lo, hi);  sumA[0] = lo + hi;
        unpack2(A12, sumA[1], sumA[2]); unpack2(A34, sumA[3], sumA[4]);
        unpack2(A56, sumA[5], sumA[6]); unpack2(A78, sumA[7], sumA[8]);
        unpack2(dB, lo, hi);  sumB[0] = lo + hi;
        unpack2(B12, sumB[1], sumB[2]); unpack2(B34, sumB[3], sumB[4]);
        unpack2(B56, sumB[5], sumB[6]); unpack2(B78, sumB[7], sumB[8]);
    } else {
        #pragma unroll
        for (int c = 0; c < CREP; c++) { sumA[c] = 0.0f; sumB[c] = 0.0f; }
        for (int n = n0; n < n0 + NCHUNK; n++) {
            float xv = s_x[n];
            const float4 ya = *(const float4*)&s_y[n * CIN];
            const float4 yb = *(const float4*)&s_y[n * CIN + 4];
            float aA = xv - tmA, dAa = aA * aA;
            float aB = xv - tmB, dBb = aB * aB;
            sumA[0] += ex2(dAa * kk[0]);
            sumA[1] = fmaf(ex2(dAa * kk[1]), ya.x, sumA[1]);
            sumA[2] = fmaf(ex2(dAa * kk[2]), ya.y, sumA[2]);
            sumA[3] = fmaf(ex2(dAa * kk[3]), ya.z, sumA[3]);
            sumA[4] = fmaf(ex2(dAa * kk[4]), ya.w, sumA[4]);
            sumA[5] = fmaf(ex2(dAa * kk[5]), yb.x, sumA[5]);
            sumA[6] = fmaf(ex2(dAa * kk[6]), yb.y, sumA[6]);
            sumA[7] = fmaf(ex2(dAa * kk[7]), yb.z, sumA[7]);
            sumA[8] = fmaf(ex2(dAa * kk[8]), yb.w, sumA[8]);
            sumB[0] += ex2(dBb * kk[0]);
            sumB[1] = fmaf(ex2(dBb * kk[1]), ya.x, sumB[1]);
            sumB[2] = fmaf(ex2(dBb * kk[2]), ya.y, sumB[2]);
            sumB[3] = fmaf(ex2(dBb * kk[3]), ya.z, sumB[3]);
            sumB[4] = fmaf(ex2(dBb * kk[4]), ya.w, sumB[4]);
            sumB[5] = fmaf(ex2(dBb * kk[5]), yb.x, sumB[5]);
            sumB[6] = fmaf(ex2(dBb * kk[6]), yb.y, sumB[6]);
            sumB[7] = fmaf(ex2(dBb * kk[7]), yb.z, sumB[7]);
            sumB[8] = fmaf(ex2(dBb * kk[8]), yb.w, sumB[8]);
        }
    }

    // Phase 2: reduce NSPLIT partials per m. Reuse the shared pool.
    __syncthreads();
    float* red = smem;   // [NSPLIT][MBLK][CREP] = 36KB <= 40KB pool
    #pragma unroll
    for (int c = 0; c < CREP; c++) {
        red[(ns * MBLK + lane)      * CREP + c] = sumA[c];
        red[(ns * MBLK + lane + 32) * CREP + c] = sumB[c];
    }
    __syncthreads();

    if (tid < MBLK) {
        float tot[CREP];
        #pragma unroll
        for (int c = 0; c < CREP; c++) tot[c] = 0.0f;
        #pragma unroll
        for (int s = 0; s < NSPLIT; s++) {
            #pragma unroll
            for (int c = 0; c < CREP; c++)
                tot[c] += red[(s * MBLK + tid) * CREP + c];
        }

        float density = tot[0];
        float inv = 1.0f / (density + 1e-8f);
        float yv[CREP];
        yv[0] = density;
        #pragma unroll
        for (int c = 1; c < CREP; c++) yv[c] = tot[c] * inv;

        const int mout = mt * MBLK + tid;
        float* orow = gout + ((size_t)b * MVAL + mout) * COUT;
        #pragma unroll
        for (int o = 0; o < COUT; o++) {
            float r = __ldg(&gbias[o]);
            #pragma unroll
            for (int c = 0; c < CREP; c++)
                r = fmaf(__ldg(&gW[o * CREP + c]), yv[c], r);
            orow[o] = r;
        }
    }
}

extern "C" void kernel_launch(void* const* d_in, const int* in_sizes, int n_in,
                              void* d_out, int out_size) {
    const float* x     = (const float*)d_in[0];
    const float* y     = (const float*)d_in[1];
    const float* t     = (const float*)d_in[2];
    const float* sigma = (const float*)d_in[3];
    const float* W     = (const float*)d_in[4];
    const float* bias  = (const float*)d_in[5];
    float* out = (float*)d_out;

    dim3 grid(B_ * (MVAL / MBLK));   // 128 blocks x 512 threads -> single wave
    convcnp_kernel<<<grid, NTHREADS>>>(x, y, t, sigma, W, bias, out);
}